// round 11
// baseline (speedup 1.0000x reference)
#include <cuda_runtime.h>
#include <cuda_bf16.h>
#include <math.h>
#include <stdint.h>

// Problem constants (B=2, S=8192 -> T=16384), H=1024, F=2048, E=8, K=2
#define Tt    16384
#define Hd    1024
#define Fd    2048
#define NE    8
#define NSLOT 32768          // T * K
#define CAP   5120           // ceil(1.25 * T * K / E) -- exactly 40 * 128

// ---------------- static device scratch (no runtime allocation) -------------
__device__ float g_xdisp[NE * CAP * Hd];   // [E, CAP, H]
__device__ float g_gate [NE * CAP * Fd];   // [E, CAP, F]  (gate, then h in-place)
__device__ float g_y    [NE * CAP * Hd];   // [E, CAP, H]
__device__ float g_plist[NE * NSLOT];
__device__ int   g_slist[NE * NSLOT];
__device__ int   g_cnt[NE];
__device__ int   g_active[NE];
__device__ float g_imp[NE];
__device__ int   g_load[NE];
__device__ int   g_fe[NSLOT];
__device__ float g_fp[NSLOT];
__device__ int   g_pos[NSLOT];
__device__ float g_w[NSLOT];

// ---------------- per-launch counter reset ---------------------------------
__global__ void zero_kernel() {
    int i = threadIdx.x;
    if (i < NE) { g_cnt[i] = 0; g_imp[i] = 0.f; g_load[i] = 0; }
}

// ---------------- router ----------------------------------------------------
__global__ void router_kernel(const float* __restrict__ x,
                              const float* __restrict__ Wr) {
    __shared__ float sWr[Hd * NE];
    __shared__ float s_imp[NE];
    __shared__ int   s_load[NE];
    int tid = threadIdx.x;
    if (tid < NE) { s_imp[tid] = 0.f; s_load[tid] = 0; }
    for (int i = tid; i < Hd * NE / 4; i += 256)
        ((float4*)sWr)[i] = ((const float4*)Wr)[i];
    __syncthreads();

    int warp = tid >> 5, lane = tid & 31;
    int t = blockIdx.x * 8 + warp;

    float acc[NE];
#pragma unroll
    for (int e = 0; e < NE; e++) acc[e] = 0.f;

    const float* xr = x + (size_t)t * Hd;
    for (int j = lane; j < Hd; j += 32) {
        float xv = xr[j];
#pragma unroll
        for (int e = 0; e < NE; e++) acc[e] += xv * sWr[j * NE + e];
    }
#pragma unroll
    for (int o = 16; o; o >>= 1)
#pragma unroll
        for (int e = 0; e < NE; e++)
            acc[e] += __shfl_xor_sync(0xffffffffu, acc[e], o);

    if (lane == 0) {
        float mx = acc[0];
#pragma unroll
        for (int e = 1; e < NE; e++) mx = fmaxf(mx, acc[e]);
        float pe[NE], s = 0.f;
#pragma unroll
        for (int e = 0; e < NE; e++) { pe[e] = expf(acc[e] - mx); s += pe[e]; }
        float inv = 1.f / s;
#pragma unroll
        for (int e = 0; e < NE; e++) { pe[e] *= inv; atomicAdd(&s_imp[e], pe[e]); }
        int e0 = 0;
#pragma unroll
        for (int e = 1; e < NE; e++) if (pe[e] > pe[e0]) e0 = e;
        int e1 = (e0 == 0) ? 1 : 0;
#pragma unroll
        for (int e = 0; e < NE; e++)
            if (e != e0 && e != e1 && pe[e] > pe[e1]) e1 = e;
        atomicAdd(&s_load[e0], 1);
        atomicAdd(&s_load[e1], 1);
        float ps = pe[e0] + pe[e1];
        g_fe[2 * t]     = e0;
        g_fe[2 * t + 1] = e1;
        g_fp[2 * t]     = pe[e0] / ps;
        g_fp[2 * t + 1] = pe[e1] / ps;
    }
    __syncthreads();
    if (tid < NE) {
        atomicAdd(&g_imp[tid], s_imp[tid]);
        atomicAdd(&g_load[tid], s_load[tid]);
    }
}

// ---------------- group slots by expert -------------------------------------
__global__ void build_lists() {
    int n = blockIdx.x * 256 + threadIdx.x;
    if (n >= NSLOT) return;
    int e = g_fe[n];
    int i = atomicAdd(&g_cnt[e], 1);
    g_plist[e * NSLOT + i] = g_fp[n];
    g_slist[e * NSLOT + i] = n;
}

__global__ void finalize_kernel() {
    int e = threadIdx.x;
    if (e < NE) g_active[e] = min(g_cnt[e], CAP);
}

// ---------------- exact stable descending rank per expert -------------------
__global__ void rank_kernel() {
    int gw   = (blockIdx.x * blockDim.x + threadIdx.x) >> 5;
    int lane = threadIdx.x & 31;
    if (gw >= NSLOT) return;
    int n = gw;
    int e = g_fe[n];
    float p = g_fp[n];
    int c = g_cnt[e];
    const float* pl = g_plist + e * NSLOT;
    const int*   sl = g_slist + e * NSLOT;
    int r = 0;
    for (int i = lane; i < c; i += 32) {
        float pm = pl[i];
        if (pm > p || (pm == p && sl[i] < n)) r++;
    }
#pragma unroll
    for (int o = 16; o; o >>= 1) r += __shfl_xor_sync(0xffffffffu, r, o);
    if (lane == 0) {
        bool keep = r < CAP;
        g_pos[n] = keep ? r : (CAP - 1);
        g_w[n]   = keep ? p : 0.f;
    }
}

// ---------------- dispatch ----------------------------------------------------
__global__ void scatter_kernel(const float* __restrict__ x) {
    int n = blockIdx.x;
    float w = g_w[n];
    if (w == 0.f) return;
    int e = g_fe[n], pos = g_pos[n];
    int t = n >> 1;
    const float4* src = (const float4*)(x + (size_t)t * Hd);
    float4* dst = (float4*)(g_xdisp + ((size_t)e * CAP + pos) * Hd);
    int tid = threadIdx.x;
    dst[tid]       = src[tid];
    dst[tid + 128] = src[tid + 128];
}

// ================= bf16x3 tensor-core grouped GEMM ===========================
// Block tile 128x128x32, 8 warps (4 x 2), warp tile 32x64, m16n8k16 bf16 mma.
// Truncation split: hi = trunc16(x), lo = rn_bf16(x - hi).
// acc += hi*hi + hi*lo + lo*hi (fp32 accumulate).
// Round-9 structure (two barriers per k-tile, prefetch between them), but
// __launch_bounds__(256, 2): two co-resident CTAs per SM so one CTA's MMA
// bursts cover the other's barrier/ldsm latency bubbles.
// mode 0: gate = x_disp @ Wg
// mode 1: h    = silu(gate) * (x_disp @ Wu)   (in place over gate buffer)
// mode 2: y    = h @ W2

#define SA_STRIDE 40      // bf16 elems per A smem row (padded from 32)
#define SB_STRIDE 136     // bf16 elems per B smem row (padded from 128)
#define A_BYTES   10240   // 128 * SA_STRIDE * 2
#define B_BYTES   8704    // 32 * SB_STRIDE * 2
#define BUF_BYTES 37888   // 2*A_BYTES + 2*B_BYTES  (Ahi, Alo, Bhi, Blo)
#define SMEM_GEMM 75776   // 2 * BUF_BYTES (x2 CTAs = 151.5 KB < 228 KB)

// fast truncation split: 2 floats -> packed bf16 hi pair + packed bf16 lo pair
__device__ __forceinline__ void split2(float x, float y, uint32_t& hi, uint32_t& lo) {
    uint32_t ux = __float_as_uint(x);
    uint32_t uy = __float_as_uint(y);
    hi = __byte_perm(ux, uy, 0x7632);            // {hi(x) low16, hi(y) high16}
    float lx = x - __uint_as_float(ux & 0xFFFF0000u);   // exact residual
    float ly = y - __uint_as_float(uy & 0xFFFF0000u);
    asm("cvt.rn.bf16x2.f32 %0, %1, %2;" : "=r"(lo) : "f"(ly), "f"(lx));
}

__device__ __forceinline__ void ldsm4(uint32_t* r, uint32_t addr) {
    asm volatile("ldmatrix.sync.aligned.m8n8.x4.shared.b16 {%0,%1,%2,%3}, [%4];"
        : "=r"(r[0]), "=r"(r[1]), "=r"(r[2]), "=r"(r[3]) : "r"(addr));
}
__device__ __forceinline__ void ldsm4t(uint32_t* r, uint32_t addr) {
    asm volatile("ldmatrix.sync.aligned.m8n8.x4.trans.shared.b16 {%0,%1,%2,%3}, [%4];"
        : "=r"(r[0]), "=r"(r[1]), "=r"(r[2]), "=r"(r[3]) : "r"(addr));
}
__device__ __forceinline__ void mma16816(float* d, const uint32_t* a, uint32_t b0, uint32_t b1) {
    asm volatile("mma.sync.aligned.m16n8k16.row.col.f32.bf16.bf16.f32 "
        "{%0,%1,%2,%3}, {%4,%5,%6,%7}, {%8,%9}, {%0,%1,%2,%3};"
        : "+f"(d[0]), "+f"(d[1]), "+f"(d[2]), "+f"(d[3])
        : "r"(a[0]), "r"(a[1]), "r"(a[2]), "r"(a[3]), "r"(b0), "r"(b1));
}

__global__ __launch_bounds__(256, 2) void mma_gemm(
    const float* __restrict__ Ball, int K, int N, int mode) {
    int e = blockIdx.z;
    int row0 = blockIdx.y * 128;
    if (row0 >= g_active[e]) return;

    const float* A = (mode == 2 ? g_gate : g_xdisp) + (size_t)e * CAP * K;
    const float* B = Ball + (size_t)e * K * N;
    float*       C = (mode == 2 ? g_y : g_gate) + (size_t)e * CAP * N;
    int col0 = blockIdx.x * 128;

    extern __shared__ char smem[];
    uint32_t sbase = (uint32_t)__cvta_generic_to_shared(smem);

    int tid  = threadIdx.x;
    int lane = tid & 31, wid = tid >> 5;
    int wm = wid >> 1, wn = wid & 1;          // 4 x 2 warp grid

    // gmem staging layout
    int arow = tid >> 1, acol = (tid & 1) * 16;   // A: 128 rows x 32 cols
    int brow = tid >> 3, bcol = (tid & 7) * 16;   // B: 32 rows x 128 cols
    const float* Ag = A + (size_t)(row0 + arow) * K + acol;
    const float* Bg = B + (size_t)brow * N + col0 + bcol;

    float4 avr[4], bvr[4];
#pragma unroll
    for (int i = 0; i < 4; i++) avr[i] = *(const float4*)(Ag + i * 4);
#pragma unroll
    for (int i = 0; i < 4; i++) bvr[i] = *(const float4*)(Bg + i * 4);

    float acc[2][8][4];
#pragma unroll
    for (int mi = 0; mi < 2; mi++)
#pragma unroll
        for (int ni = 0; ni < 8; ni++)
#pragma unroll
            for (int k = 0; k < 4; k++) acc[mi][ni][k] = 0.f;

    int kTiles = K >> 5;
    for (int kt = 0; kt < kTiles; ++kt) {
        int cur = kt & 1;
        char* bufp = smem + cur * BUF_BYTES;

        // store staged regs (truncation-split hi/lo) to smem
#pragma unroll
        for (int i = 0; i < 4; i++) {
            uint32_t h0, l0, h1, l1;
            split2(avr[i].x, avr[i].y, h0, l0);
            split2(avr[i].z, avr[i].w, h1, l1);
            int off = arow * (SA_STRIDE * 2) + (acol + i * 4) * 2;
            *(uint2*)(bufp + off)           = make_uint2(h0, h1);
            *(uint2*)(bufp + A_BYTES + off) = make_uint2(l0, l1);
        }
#pragma unroll
        for (int i = 0; i < 4; i++) {
            uint32_t h0, l0, h1, l1;
            split2(bvr[i].x, bvr[i].y, h0, l0);
            split2(bvr[i].z, bvr[i].w, h1, l1);
            int off = brow * (SB_STRIDE * 2) + (bcol + i * 4) * 2;
            *(uint2*)(bufp + 2 * A_BYTES + off)           = make_uint2(h0, h1);
            *(uint2*)(bufp + 2 * A_BYTES + B_BYTES + off) = make_uint2(l0, l1);
        }
        __syncthreads();

        // prefetch next tile into registers
        if (kt + 1 < kTiles) {
            Ag += 32;
            Bg += (size_t)32 * N;
#pragma unroll
            for (int i = 0; i < 4; i++) avr[i] = *(const float4*)(Ag + i * 4);
#pragma unroll
            for (int i = 0; i < 4; i++) bvr[i] = *(const float4*)(Bg + i * 4);
        }

        // compute
        uint32_t sA = sbase + cur * BUF_BYTES;
        uint32_t sB = sA + 2 * A_BYTES;
#pragma unroll
        for (int ks = 0; ks < 2; ks++) {
            uint32_t ah[2][4], al[2][4], bh[4][4], bl[4][4];
#pragma unroll
            for (int mi = 0; mi < 2; mi++) {
                uint32_t r = wm * 32 + mi * 16 + (lane & 15);
                uint32_t c = ks * 16 + ((lane >> 4) << 3);
                uint32_t addr = sA + (r * SA_STRIDE + c) * 2;
                ldsm4(ah[mi], addr);
                ldsm4(al[mi], addr + A_BYTES);
            }
#pragma unroll
            for (int nb = 0; nb < 4; nb++) {
                uint32_t r = ks * 16 + (lane & 15);
                uint32_t c = wn * 64 + nb * 16 + ((lane >> 4) << 3);
                uint32_t addr = sB + (r * SB_STRIDE + c) * 2;
                ldsm4t(bh[nb], addr);
                ldsm4t(bl[nb], addr + B_BYTES);
            }
#pragma unroll
            for (int mi = 0; mi < 2; mi++)
#pragma unroll
                for (int nb = 0; nb < 4; nb++)
#pragma unroll
                    for (int j = 0; j < 2; j++) {
                        int ni = nb * 2 + j;
                        mma16816(acc[mi][ni], ah[mi], bh[nb][2 * j], bh[nb][2 * j + 1]);
                        mma16816(acc[mi][ni], ah[mi], bl[nb][2 * j], bl[nb][2 * j + 1]);
                        mma16816(acc[mi][ni], al[mi], bh[nb][2 * j], bh[nb][2 * j + 1]);
                    }
        }
        __syncthreads();
    }

    // epilogue
    int gq = lane >> 2, q = lane & 3;
#pragma unroll
    for (int mi = 0; mi < 2; mi++) {
        int r = row0 + wm * 32 + mi * 16 + gq;
#pragma unroll
        for (int ni = 0; ni < 8; ni++) {
            int c = col0 + wn * 64 + ni * 8 + q * 2;
            size_t i0 = (size_t)r * N + c;
            size_t i1 = i0 + (size_t)8 * N;
            float2 v0, v1;
            if (mode == 1) {
                float2 g0 = *(const float2*)&C[i0];
                float2 g1 = *(const float2*)&C[i1];
                v0.x = g0.x / (1.f + expf(-g0.x)) * acc[mi][ni][0];
                v0.y = g0.y / (1.f + expf(-g0.y)) * acc[mi][ni][1];
                v1.x = g1.x / (1.f + expf(-g1.x)) * acc[mi][ni][2];
                v1.y = g1.y / (1.f + expf(-g1.y)) * acc[mi][ni][3];
            } else {
                v0 = make_float2(acc[mi][ni][0], acc[mi][ni][1]);
                v1 = make_float2(acc[mi][ni][2], acc[mi][ni][3]);
            }
            *(float2*)&C[i0] = v0;
            *(float2*)&C[i1] = v1;
        }
    }
}

// ---------------- combine ----------------------------------------------------
__global__ void combine_kernel(float* __restrict__ out) {
    int t = blockIdx.x;
    int tid = threadIdx.x;
    int n0 = 2 * t, n1 = 2 * t + 1;
    float w0 = g_w[n0], w1 = g_w[n1];
    const float4* y0 = (const float4*)(g_y + ((size_t)g_fe[n0] * CAP + g_pos[n0]) * Hd);
    const float4* y1 = (const float4*)(g_y + ((size_t)g_fe[n1] * CAP + g_pos[n1]) * Hd);
    float4 a = y0[tid], b = y1[tid];
    float4 o;
    o.x = w0 * a.x + w1 * b.x;
    o.y = w0 * a.y + w1 * b.y;
    o.z = w0 * a.z + w1 * b.z;
    o.w = w0 * a.w + w1 * b.w;
    ((float4*)(out + (size_t)t * Hd))[tid] = o;
}

// ---------------- aux loss -----------------------------------------------------
__global__ void aux_kernel(float* __restrict__ out, int out_size) {
    if (threadIdx.x == 0) {
        float s = 0.f;
#pragma unroll
        for (int e = 0; e < NE; e++) s += g_imp[e] * (float)g_load[e];
        float aux = (float)NE * s / (float)(Tt * 2);
        if (out_size > Tt * Hd) out[(size_t)Tt * Hd] = aux;
    }
}

// ---------------- launch -------------------------------------------------------
extern "C" void kernel_launch(void* const* d_in, const int* in_sizes, int n_in,
                              void* d_out, int out_size) {
    const float* x  = (const float*)d_in[0];
    const float* Wr = (const float*)d_in[1];
    const float* Wg = (const float*)d_in[2];
    const float* Wu = (const float*)d_in[3];
    const float* W2 = (const float*)d_in[4];
    float* out = (float*)d_out;

    int smem_bytes = SMEM_GEMM;
    cudaFuncSetAttribute(mma_gemm, cudaFuncAttributeMaxDynamicSharedMemorySize, smem_bytes);

    zero_kernel<<<1, 32>>>();
    router_kernel<<<Tt / 8, 256>>>(x, Wr);
    build_lists<<<NSLOT / 256, 256>>>();
    finalize_kernel<<<1, 32>>>();
    rank_kernel<<<NSLOT / 8, 256>>>();
    scatter_kernel<<<NSLOT, 128>>>(x);

    dim3 grid_ff(Fd / 128, CAP / 128, NE);
    dim3 grid_w2(Hd / 128, CAP / 128, NE);

    mma_gemm<<<grid_ff, 256, smem_bytes>>>(Wg, Hd, Fd, 0);   // gate
    mma_gemm<<<grid_ff, 256, smem_bytes>>>(Wu, Hd, Fd, 1);   // h = silu(gate)*up
    mma_gemm<<<grid_w2, 256, smem_bytes>>>(W2, Fd, Hd, 2);   // y

    combine_kernel<<<Tt, 256>>>(out);
    aux_kernel<<<1, 32>>>(out, out_size);
}

// round 12
// speedup vs baseline: 1.1160x; 1.1160x over previous
#include <cuda_runtime.h>
#include <cuda_bf16.h>
#include <math.h>
#include <stdint.h>

// Problem constants (B=2, S=8192 -> T=16384), H=1024, F=2048, E=8, K=2
#define Tt    16384
#define Hd    1024
#define Fd    2048
#define NE    8
#define NSLOT 32768          // T * K
#define CAP   5120           // ceil(1.25 * T * K / E) -- exactly 40 * 128

// ---------------- static device scratch (no runtime allocation) -------------
__device__ float    g_xdisp[NE * CAP * Hd];
__device__ float    g_gate [NE * CAP * Fd];   // gate, then h in-place
__device__ float    g_y    [NE * CAP * Hd];
__device__ unsigned long long g_keys[NE * NSLOT];  // packed sort keys per expert
__device__ int   g_cnt[NE];
__device__ int   g_active[NE];
__device__ float g_imp[NE];
__device__ int   g_load[NE];
__device__ int   g_fe[NSLOT];
__device__ float g_fp[NSLOT];
__device__ int   g_pos[NSLOT];
__device__ float g_w[NSLOT];

// ---------------- per-launch counter reset ---------------------------------
__global__ void zero_kernel() {
    int i = threadIdx.x;
    if (i < NE) { g_cnt[i] = 0; g_imp[i] = 0.f; g_load[i] = 0; }
}

// ---------------- router ----------------------------------------------------
__global__ void router_kernel(const float* __restrict__ x,
                              const float* __restrict__ Wr) {
    __shared__ float sWr[Hd * NE];
    __shared__ float s_imp[NE];
    __shared__ int   s_load[NE];
    int tid = threadIdx.x;
    if (tid < NE) { s_imp[tid] = 0.f; s_load[tid] = 0; }
    for (int i = tid; i < Hd * NE / 4; i += 256)
        ((float4*)sWr)[i] = ((const float4*)Wr)[i];
    __syncthreads();

    int warp = tid >> 5, lane = tid & 31;
    int t = blockIdx.x * 8 + warp;

    float acc[NE];
#pragma unroll
    for (int e = 0; e < NE; e++) acc[e] = 0.f;

    const float* xr = x + (size_t)t * Hd;
    for (int j = lane; j < Hd; j += 32) {
        float xv = xr[j];
#pragma unroll
        for (int e = 0; e < NE; e++) acc[e] += xv * sWr[j * NE + e];
    }
#pragma unroll
    for (int o = 16; o; o >>= 1)
#pragma unroll
        for (int e = 0; e < NE; e++)
            acc[e] += __shfl_xor_sync(0xffffffffu, acc[e], o);

    if (lane == 0) {
        float mx = acc[0];
#pragma unroll
        for (int e = 1; e < NE; e++) mx = fmaxf(mx, acc[e]);
        float pe[NE], s = 0.f;
#pragma unroll
        for (int e = 0; e < NE; e++) { pe[e] = expf(acc[e] - mx); s += pe[e]; }
        float inv = 1.f / s;
#pragma unroll
        for (int e = 0; e < NE; e++) { pe[e] *= inv; atomicAdd(&s_imp[e], pe[e]); }
        int e0 = 0;
#pragma unroll
        for (int e = 1; e < NE; e++) if (pe[e] > pe[e0]) e0 = e;
        int e1 = (e0 == 0) ? 1 : 0;
#pragma unroll
        for (int e = 0; e < NE; e++)
            if (e != e0 && e != e1 && pe[e] > pe[e1]) e1 = e;
        atomicAdd(&s_load[e0], 1);
        atomicAdd(&s_load[e1], 1);
        float ps = pe[e0] + pe[e1];
        g_fe[2 * t]     = e0;
        g_fe[2 * t + 1] = e1;
        g_fp[2 * t]     = pe[e0] / ps;
        g_fp[2 * t + 1] = pe[e1] / ps;
    }
    __syncthreads();
    if (tid < NE) {
        atomicAdd(&g_imp[tid], s_imp[tid]);
        atomicAdd(&g_load[tid], s_load[tid]);
    }
}

// ---------------- group slots by expert: packed keys -------------------------
// key = (prob_bits << 32) | (NSLOT-1-n). probs > 0 so IEEE bits order like
// floats; key_m > key_n  <=>  p_m > p_n || (p_m == p_n && m < n).  Exact.
__global__ void build_lists() {
    int n = blockIdx.x * 256 + threadIdx.x;
    if (n >= NSLOT) return;
    int e = g_fe[n];
    int i = atomicAdd(&g_cnt[e], 1);
    unsigned long long key =
        ((unsigned long long)__float_as_uint(g_fp[n]) << 32) |
        (unsigned int)(NSLOT - 1 - n);
    g_keys[e * NSLOT + i] = key;
}

__global__ void finalize_kernel() {
    int e = threadIdx.x;
    if (e < NE) g_active[e] = min(g_cnt[e], CAP);
}

// ---------------- rank: smem-tiled exact descending rank ---------------------
// grid (NSLOT/256, NE); block handles 256 entries of expert e's key list,
// scanning the whole list through shared memory (gmem traffic ~cnt per block).
__global__ void rank_kernel() {
    int e = blockIdx.y;
    int c = g_cnt[e];
    int base = blockIdx.x * 256;
    if (base >= c) return;
    __shared__ unsigned long long sk[512];
    int tid = threadIdx.x;
    int idx = base + tid;
    bool act = idx < c;
    unsigned long long key = 0;
    if (act) key = g_keys[e * NSLOT + idx];
    int r = 0;
    for (int chunk = 0; chunk < c; chunk += 512) {
        int m = min(512, c - chunk);
        for (int i = tid; i < m; i += 256)
            sk[i] = g_keys[e * NSLOT + chunk + i];
        __syncthreads();
        if (act)
            for (int i = 0; i < m; i++)
                if (sk[i] > key) r++;
        __syncthreads();
    }
    if (act) {
        int n = NSLOT - 1 - (int)(unsigned int)(key & 0xFFFFFFFFu);
        float p = __uint_as_float((unsigned int)(key >> 32));
        bool keep = r < CAP;
        g_pos[n] = keep ? r : (CAP - 1);
        g_w[n]   = keep ? p : 0.f;
    }
}

// ---------------- dispatch ----------------------------------------------------
__global__ void scatter_kernel(const float* __restrict__ x) {
    int n = blockIdx.x;
    float w = g_w[n];
    if (w == 0.f) return;
    int e = g_fe[n], pos = g_pos[n];
    int t = n >> 1;
    const float4* src = (const float4*)(x + (size_t)t * Hd);
    float4* dst = (float4*)(g_xdisp + ((size_t)e * CAP + pos) * Hd);
    int tid = threadIdx.x;
    dst[tid]       = src[tid];
    dst[tid + 128] = src[tid + 128];
}

// ================= bf16x3 tensor-core grouped GEMM ===========================
// Block tile 128x128x32, 512 threads (16 warps, 4x4 grid), warp tile 32x32,
// m16n8k16 bf16 mma. Truncation split hi/lo; acc += hh + hl + lh (fp32).
// Two barriers per k-tile (round-9 proven structure); 4 warps/SMSP for
// latency hiding; ~95 regs/thread so no spills.
// mode 0: gate = x_disp @ Wg
// mode 1: h    = silu(gate) * (x_disp @ Wu)   (in place over gate buffer)
// mode 2: y    = h @ W2

#define SA_STRIDE 40      // bf16 elems per A smem row (padded from 32)
#define SB_STRIDE 136     // bf16 elems per B smem row (padded from 128)
#define A_BYTES   10240   // 128 * SA_STRIDE * 2
#define B_BYTES   8704    // 32 * SB_STRIDE * 2
#define BUF_BYTES 37888   // Ahi + Alo + Bhi + Blo
#define SMEM_GEMM 75776   // 2 buffers

// fast truncation split: 2 floats -> packed bf16 hi pair + packed bf16 lo pair
__device__ __forceinline__ void split2(float x, float y, uint32_t& hi, uint32_t& lo) {
    uint32_t ux = __float_as_uint(x);
    uint32_t uy = __float_as_uint(y);
    hi = __byte_perm(ux, uy, 0x7632);
    float lx = x - __uint_as_float(ux & 0xFFFF0000u);
    float ly = y - __uint_as_float(uy & 0xFFFF0000u);
    asm("cvt.rn.bf16x2.f32 %0, %1, %2;" : "=r"(lo) : "f"(ly), "f"(lx));
}

__device__ __forceinline__ void ldsm4(uint32_t* r, uint32_t addr) {
    asm volatile("ldmatrix.sync.aligned.m8n8.x4.shared.b16 {%0,%1,%2,%3}, [%4];"
        : "=r"(r[0]), "=r"(r[1]), "=r"(r[2]), "=r"(r[3]) : "r"(addr));
}
__device__ __forceinline__ void ldsm4t(uint32_t* r, uint32_t addr) {
    asm volatile("ldmatrix.sync.aligned.m8n8.x4.trans.shared.b16 {%0,%1,%2,%3}, [%4];"
        : "=r"(r[0]), "=r"(r[1]), "=r"(r[2]), "=r"(r[3]) : "r"(addr));
}
__device__ __forceinline__ void mma16816(float* d, const uint32_t* a, uint32_t b0, uint32_t b1) {
    asm volatile("mma.sync.aligned.m16n8k16.row.col.f32.bf16.bf16.f32 "
        "{%0,%1,%2,%3}, {%4,%5,%6,%7}, {%8,%9}, {%0,%1,%2,%3};"
        : "+f"(d[0]), "+f"(d[1]), "+f"(d[2]), "+f"(d[3])
        : "r"(a[0]), "r"(a[1]), "r"(a[2]), "r"(a[3]), "r"(b0), "r"(b1));
}

__global__ __launch_bounds__(512, 1) void mma_gemm(
    const float* __restrict__ Ball, int K, int N, int mode) {
    int e = blockIdx.z;
    int row0 = blockIdx.y * 128;
    if (row0 >= g_active[e]) return;

    const float* A = (mode == 2 ? g_gate : g_xdisp) + (size_t)e * CAP * K;
    const float* B = Ball + (size_t)e * K * N;
    float*       C = (mode == 2 ? g_y : g_gate) + (size_t)e * CAP * N;
    int col0 = blockIdx.x * 128;

    extern __shared__ char smem[];
    uint32_t sbase = (uint32_t)__cvta_generic_to_shared(smem);

    int tid  = threadIdx.x;
    int lane = tid & 31, wid = tid >> 5;
    int wm = wid >> 2, wn = wid & 3;          // 4 x 4 warp grid, tile 32x32

    // gmem staging: A 128x32 (4 thr/row, 8 floats each); B 32x128 (16 thr/row)
    int arow = tid >> 2,  acol = (tid & 3) * 8;
    int brow = tid >> 4,  bcol = (tid & 15) * 8;
    const float* Ag = A + (size_t)(row0 + arow) * K + acol;
    const float* Bg = B + (size_t)brow * N + col0 + bcol;

    float4 avr[2], bvr[2];
    avr[0] = *(const float4*)Ag;       avr[1] = *(const float4*)(Ag + 4);
    bvr[0] = *(const float4*)Bg;       bvr[1] = *(const float4*)(Bg + 4);

    float acc[2][4][4];
#pragma unroll
    for (int mi = 0; mi < 2; mi++)
#pragma unroll
        for (int ni = 0; ni < 4; ni++)
#pragma unroll
            for (int k = 0; k < 4; k++) acc[mi][ni][k] = 0.f;

    int offA = arow * 80 + acol * 2;
    int offB = brow * 272 + bcol * 2;
    int kTiles = K >> 5;

    for (int kt = 0; kt < kTiles; ++kt) {
        int cur = kt & 1;
        char* bufp = smem + cur * BUF_BYTES;

        // split + store: 8 floats -> one uint4 to hi plane, one to lo plane
        {
            uint32_t h0, l0, h1, l1, h2, l2, h3, l3;
            split2(avr[0].x, avr[0].y, h0, l0);
            split2(avr[0].z, avr[0].w, h1, l1);
            split2(avr[1].x, avr[1].y, h2, l2);
            split2(avr[1].z, avr[1].w, h3, l3);
            *(uint4*)(bufp + offA)           = make_uint4(h0, h1, h2, h3);
            *(uint4*)(bufp + A_BYTES + offA) = make_uint4(l0, l1, l2, l3);
            split2(bvr[0].x, bvr[0].y, h0, l0);
            split2(bvr[0].z, bvr[0].w, h1, l1);
            split2(bvr[1].x, bvr[1].y, h2, l2);
            split2(bvr[1].z, bvr[1].w, h3, l3);
            *(uint4*)(bufp + 2 * A_BYTES + offB)           = make_uint4(h0, h1, h2, h3);
            *(uint4*)(bufp + 2 * A_BYTES + B_BYTES + offB) = make_uint4(l0, l1, l2, l3);
        }
        __syncthreads();

        // prefetch next tile
        if (kt + 1 < kTiles) {
            Ag += 32;
            Bg += (size_t)32 * N;
            avr[0] = *(const float4*)Ag;   avr[1] = *(const float4*)(Ag + 4);
            bvr[0] = *(const float4*)Bg;   bvr[1] = *(const float4*)(Bg + 4);
        }

        // compute
        uint32_t sA = sbase + cur * BUF_BYTES;
        uint32_t sB = sA + 2 * A_BYTES;
#pragma unroll
        for (int ks = 0; ks < 2; ks++) {
            uint32_t ah[2][4], al[2][4], bh[2][4], bl[2][4];
#pragma unroll
            for (int mi = 0; mi < 2; mi++) {
                uint32_t r = wm * 32 + mi * 16 + (lane & 15);
                uint32_t c = ks * 16 + ((lane >> 4) << 3);
                uint32_t addr = sA + (r * SA_STRIDE + c) * 2;
                ldsm4(ah[mi], addr);
                ldsm4(al[mi], addr + A_BYTES);
            }
#pragma unroll
            for (int nb = 0; nb < 2; nb++) {
                uint32_t r = ks * 16 + (lane & 15);
                uint32_t c = wn * 32 + nb * 16 + ((lane >> 4) << 3);
                uint32_t addr = sB + (r * SB_STRIDE + c) * 2;
                ldsm4t(bh[nb], addr);
                ldsm4t(bl[nb], addr + B_BYTES);
            }
#pragma unroll
            for (int mi = 0; mi < 2; mi++)
#pragma unroll
                for (int nb = 0; nb < 2; nb++)
#pragma unroll
                    for (int j = 0; j < 2; j++) {
                        int ni = nb * 2 + j;
                        mma16816(acc[mi][ni], ah[mi], bh[nb][2 * j], bh[nb][2 * j + 1]);
                        mma16816(acc[mi][ni], ah[mi], bl[nb][2 * j], bl[nb][2 * j + 1]);
                        mma16816(acc[mi][ni], al[mi], bh[nb][2 * j], bh[nb][2 * j + 1]);
                    }
        }
        __syncthreads();
    }

    // epilogue
    int gq = lane >> 2, q = lane & 3;
#pragma unroll
    for (int mi = 0; mi < 2; mi++) {
        int r = row0 + wm * 32 + mi * 16 + gq;
#pragma unroll
        for (int ni = 0; ni < 4; ni++) {
            int c = col0 + wn * 32 + ni * 8 + q * 2;
            size_t i0 = (size_t)r * N + c;
            size_t i1 = i0 + (size_t)8 * N;
            float2 v0, v1;
            if (mode == 1) {
                float2 g0 = *(const float2*)&C[i0];
                float2 g1 = *(const float2*)&C[i1];
                v0.x = g0.x / (1.f + expf(-g0.x)) * acc[mi][ni][0];
                v0.y = g0.y / (1.f + expf(-g0.y)) * acc[mi][ni][1];
                v1.x = g1.x / (1.f + expf(-g1.x)) * acc[mi][ni][2];
                v1.y = g1.y / (1.f + expf(-g1.y)) * acc[mi][ni][3];
            } else {
                v0 = make_float2(acc[mi][ni][0], acc[mi][ni][1]);
                v1 = make_float2(acc[mi][ni][2], acc[mi][ni][3]);
            }
            *(float2*)&C[i0] = v0;
            *(float2*)&C[i1] = v1;
        }
    }
}

// ---------------- combine ----------------------------------------------------
__global__ void combine_kernel(float* __restrict__ out) {
    int t = blockIdx.x;
    int tid = threadIdx.x;
    int n0 = 2 * t, n1 = 2 * t + 1;
    float w0 = g_w[n0], w1 = g_w[n1];
    const float4* y0 = (const float4*)(g_y + ((size_t)g_fe[n0] * CAP + g_pos[n0]) * Hd);
    const float4* y1 = (const float4*)(g_y + ((size_t)g_fe[n1] * CAP + g_pos[n1]) * Hd);
    float4 a = y0[tid], b = y1[tid];
    float4 o;
    o.x = w0 * a.x + w1 * b.x;
    o.y = w0 * a.y + w1 * b.y;
    o.z = w0 * a.z + w1 * b.z;
    o.w = w0 * a.w + w1 * b.w;
    ((float4*)(out + (size_t)t * Hd))[tid] = o;
}

// ---------------- aux loss -----------------------------------------------------
__global__ void aux_kernel(float* __restrict__ out, int out_size) {
    if (threadIdx.x == 0) {
        float s = 0.f;
#pragma unroll
        for (int e = 0; e < NE; e++) s += g_imp[e] * (float)g_load[e];
        float aux = (float)NE * s / (float)(Tt * 2);
        if (out_size > Tt * Hd) out[(size_t)Tt * Hd] = aux;
    }
}

// ---------------- launch -------------------------------------------------------
extern "C" void kernel_launch(void* const* d_in, const int* in_sizes, int n_in,
                              void* d_out, int out_size) {
    const float* x  = (const float*)d_in[0];
    const float* Wr = (const float*)d_in[1];
    const float* Wg = (const float*)d_in[2];
    const float* Wu = (const float*)d_in[3];
    const float* W2 = (const float*)d_in[4];
    float* out = (float*)d_out;

    int smem_bytes = SMEM_GEMM;
    cudaFuncSetAttribute(mma_gemm, cudaFuncAttributeMaxDynamicSharedMemorySize, smem_bytes);

    zero_kernel<<<1, 32>>>();
    router_kernel<<<Tt / 8, 256>>>(x, Wr);
    build_lists<<<NSLOT / 256, 256>>>();
    finalize_kernel<<<1, 32>>>();
    rank_kernel<<<dim3(NSLOT / 256, NE), 256>>>();
    scatter_kernel<<<NSLOT, 128>>>(x);

    dim3 grid_ff(Fd / 128, CAP / 128, NE);
    dim3 grid_w2(Hd / 128, CAP / 128, NE);

    mma_gemm<<<grid_ff, 512, smem_bytes>>>(Wg, Hd, Fd, 0);   // gate
    mma_gemm<<<grid_ff, 512, smem_bytes>>>(Wu, Hd, Fd, 1);   // h = silu(gate)*up
    mma_gemm<<<grid_w2, 512, smem_bytes>>>(W2, Fd, Hd, 2);   // y

    combine_kernel<<<Tt, 256>>>(out);
    aux_kernel<<<1, 32>>>(out, out_size);
}

// round 13
// speedup vs baseline: 1.2041x; 1.0790x over previous
#include <cuda_runtime.h>
#include <cuda_bf16.h>
#include <math.h>
#include <stdint.h>

// Problem constants (B=2, S=8192 -> T=16384), H=1024, F=2048, E=8, K=2
#define Tt    16384
#define Hd    1024
#define Fd    2048
#define NE    8
#define NSLOT 32768          // T * K
#define CAP   5120           // ceil(1.25 * T * K / E) -- exactly 40 * 128

// ---------------- static device scratch (no runtime allocation) -------------
__device__ float    g_xdisp[NE * CAP * Hd];
__device__ float    g_h    [NE * CAP * Fd];   // h = silu(gate)*up (fp32)
__device__ float    g_y    [NE * CAP * Hd];
__device__ unsigned long long g_keys[NE * NSLOT];
__device__ int   g_cnt[NE];
__device__ int   g_active[NE];
__device__ float g_imp[NE];
__device__ int   g_load[NE];
__device__ int   g_fe[NSLOT];
__device__ float g_fp[NSLOT];
__device__ int   g_pos[NSLOT];
__device__ float g_w[NSLOT];

// ---------------- per-launch counter reset ---------------------------------
__global__ void zero_kernel() {
    int i = threadIdx.x;
    if (i < NE) { g_cnt[i] = 0; g_imp[i] = 0.f; g_load[i] = 0; }
}

// ---------------- router ----------------------------------------------------
__global__ void router_kernel(const float* __restrict__ x,
                              const float* __restrict__ Wr) {
    __shared__ float sWr[Hd * NE];
    __shared__ float s_imp[NE];
    __shared__ int   s_load[NE];
    int tid = threadIdx.x;
    if (tid < NE) { s_imp[tid] = 0.f; s_load[tid] = 0; }
    for (int i = tid; i < Hd * NE / 4; i += 256)
        ((float4*)sWr)[i] = ((const float4*)Wr)[i];
    __syncthreads();

    int warp = tid >> 5, lane = tid & 31;
    int t = blockIdx.x * 8 + warp;

    float acc[NE];
#pragma unroll
    for (int e = 0; e < NE; e++) acc[e] = 0.f;

    const float* xr = x + (size_t)t * Hd;
    for (int j = lane; j < Hd; j += 32) {
        float xv = xr[j];
#pragma unroll
        for (int e = 0; e < NE; e++) acc[e] += xv * sWr[j * NE + e];
    }
#pragma unroll
    for (int o = 16; o; o >>= 1)
#pragma unroll
        for (int e = 0; e < NE; e++)
            acc[e] += __shfl_xor_sync(0xffffffffu, acc[e], o);

    if (lane == 0) {
        float mx = acc[0];
#pragma unroll
        for (int e = 1; e < NE; e++) mx = fmaxf(mx, acc[e]);
        float pe[NE], s = 0.f;
#pragma unroll
        for (int e = 0; e < NE; e++) { pe[e] = expf(acc[e] - mx); s += pe[e]; }
        float inv = 1.f / s;
#pragma unroll
        for (int e = 0; e < NE; e++) { pe[e] *= inv; atomicAdd(&s_imp[e], pe[e]); }
        int e0 = 0;
#pragma unroll
        for (int e = 1; e < NE; e++) if (pe[e] > pe[e0]) e0 = e;
        int e1 = (e0 == 0) ? 1 : 0;
#pragma unroll
        for (int e = 0; e < NE; e++)
            if (e != e0 && e != e1 && pe[e] > pe[e1]) e1 = e;
        atomicAdd(&s_load[e0], 1);
        atomicAdd(&s_load[e1], 1);
        float ps = pe[e0] + pe[e1];
        g_fe[2 * t]     = e0;
        g_fe[2 * t + 1] = e1;
        g_fp[2 * t]     = pe[e0] / ps;
        g_fp[2 * t + 1] = pe[e1] / ps;
    }
    __syncthreads();
    if (tid < NE) {
        atomicAdd(&g_imp[tid], s_imp[tid]);
        atomicAdd(&g_load[tid], s_load[tid]);
    }
}

// ---------------- group slots by expert: packed keys -------------------------
// key = (prob_bits << 32) | (NSLOT-1-n); exact order: p desc, index asc.
__global__ void build_lists() {
    int n = blockIdx.x * 256 + threadIdx.x;
    if (n >= NSLOT) return;
    int e = g_fe[n];
    int i = atomicAdd(&g_cnt[e], 1);
    unsigned long long key =
        ((unsigned long long)__float_as_uint(g_fp[n]) << 32) |
        (unsigned int)(NSLOT - 1 - n);
    g_keys[e * NSLOT + i] = key;
}

__global__ void finalize_kernel() {
    int e = threadIdx.x;
    if (e < NE) g_active[e] = min(g_cnt[e], CAP);
}

// ---------------- rank: smem-tiled exact descending rank ---------------------
__global__ void rank_kernel() {
    int e = blockIdx.y;
    int c = g_cnt[e];
    int base = blockIdx.x * 256;
    if (base >= c) return;
    __shared__ unsigned long long sk[512];
    int tid = threadIdx.x;
    int idx = base + tid;
    bool act = idx < c;
    unsigned long long key = 0;
    if (act) key = g_keys[e * NSLOT + idx];
    int r = 0;
    for (int chunk = 0; chunk < c; chunk += 512) {
        int m = min(512, c - chunk);
        for (int i = tid; i < m; i += 256)
            sk[i] = g_keys[e * NSLOT + chunk + i];
        __syncthreads();
        if (act)
            for (int i = 0; i < m; i++)
                if (sk[i] > key) r++;
        __syncthreads();
    }
    if (act) {
        int n = NSLOT - 1 - (int)(unsigned int)(key & 0xFFFFFFFFu);
        float p = __uint_as_float((unsigned int)(key >> 32));
        bool keep = r < CAP;
        g_pos[n] = keep ? r : (CAP - 1);
        g_w[n]   = keep ? p : 0.f;
    }
}

// ---------------- dispatch ----------------------------------------------------
__global__ void scatter_kernel(const float* __restrict__ x) {
    int n = blockIdx.x;
    float w = g_w[n];
    if (w == 0.f) return;
    int e = g_fe[n], pos = g_pos[n];
    int t = n >> 1;
    const float4* src = (const float4*)(x + (size_t)t * Hd);
    float4* dst = (float4*)(g_xdisp + ((size_t)e * CAP + pos) * Hd);
    int tid = threadIdx.x;
    dst[tid]       = src[tid];
    dst[tid + 128] = src[tid + 128];
}

// ================= bf16x3 tensor-core grouped GEMM ===========================
// Round-9 proven shape: block 128x128x32, 8 warps (4x2), warp tile 32x64,
// two barriers per k-tile, truncation split, acc += hh + hl + lh.

#define SA_STRIDE 40
#define SB_STRIDE 136
#define A_BYTES   10240   // 128 * 80
#define B_BYTES   8704    // 32 * 272
#define BUF_BYTES 37888
#define SMEM_GEMM 75776

__device__ __forceinline__ void split2(float x, float y, uint32_t& hi, uint32_t& lo) {
    uint32_t ux = __float_as_uint(x);
    uint32_t uy = __float_as_uint(y);
    hi = __byte_perm(ux, uy, 0x7632);
    float lx = x - __uint_as_float(ux & 0xFFFF0000u);
    float ly = y - __uint_as_float(uy & 0xFFFF0000u);
    asm("cvt.rn.bf16x2.f32 %0, %1, %2;" : "=r"(lo) : "f"(ly), "f"(lx));
}
__device__ __forceinline__ void ldsm4(uint32_t* r, uint32_t addr) {
    asm volatile("ldmatrix.sync.aligned.m8n8.x4.shared.b16 {%0,%1,%2,%3}, [%4];"
        : "=r"(r[0]), "=r"(r[1]), "=r"(r[2]), "=r"(r[3]) : "r"(addr));
}
__device__ __forceinline__ void ldsm4t(uint32_t* r, uint32_t addr) {
    asm volatile("ldmatrix.sync.aligned.m8n8.x4.trans.shared.b16 {%0,%1,%2,%3}, [%4];"
        : "=r"(r[0]), "=r"(r[1]), "=r"(r[2]), "=r"(r[3]) : "r"(addr));
}
__device__ __forceinline__ void mma16816(float* d, const uint32_t* a, uint32_t b0, uint32_t b1) {
    asm volatile("mma.sync.aligned.m16n8k16.row.col.f32.bf16.bf16.f32 "
        "{%0,%1,%2,%3}, {%4,%5,%6,%7}, {%8,%9}, {%0,%1,%2,%3};"
        : "+f"(d[0]), "+f"(d[1]), "+f"(d[2]), "+f"(d[3])
        : "r"(a[0]), "r"(a[1]), "r"(a[2]), "r"(a[3]), "r"(b0), "r"(b1));
}

// ---- FUSED gate+up GEMM ------------------------------------------------------
// col0 = blockIdx.x * 64 covers 64 columns of BOTH Wg and Wu.
// Smem B tile cols [0,64) <- Wg, cols [64,128) <- Wu (staged by (tid&7)<4 / >=4).
// Warps wn=0 accumulate gate, wn=1 accumulate up (same rows). Epilogue: up
// warps dump acc to smem, gate warps compute h = silu(g)*u -> g_h. No gate
// gmem round-trip.
__global__ __launch_bounds__(256, 1) void mma_fused(
    const float* __restrict__ Wg, const float* __restrict__ Wu) {
    const int K = Hd, NW = Fd;   // weight N stride
    int e = blockIdx.z;
    int row0 = blockIdx.y * 128;
    if (row0 >= g_active[e]) return;
    int col0 = blockIdx.x * 64;

    const float* A = g_xdisp + (size_t)e * CAP * K;

    extern __shared__ char smem[];
    uint32_t sbase = (uint32_t)__cvta_generic_to_shared(smem);

    int tid  = threadIdx.x;
    int lane = tid & 31, wid = tid >> 5;
    int wm = wid >> 1, wn = wid & 1;

    int arow = tid >> 1, acol = (tid & 1) * 16;
    int brow = tid >> 3, bsub = tid & 7;          // bsub*16 = bcol in [0,128)
    int bcol = bsub * 16;
    // B source: Wg for smem cols [0,64), Wu for [64,128)
    const float* Bmat = (bsub < 4) ? Wg : Wu;
    int gcol = col0 + (bcol & 63);
    const float* Ag = A + (size_t)(row0 + arow) * K + acol;
    const float* Bg = Bmat + (size_t)e * K * NW + (size_t)brow * NW + gcol;

    float4 avr[4], bvr[4];
#pragma unroll
    for (int i = 0; i < 4; i++) avr[i] = *(const float4*)(Ag + i * 4);
#pragma unroll
    for (int i = 0; i < 4; i++) bvr[i] = *(const float4*)(Bg + i * 4);

    float acc[2][8][4];
#pragma unroll
    for (int mi = 0; mi < 2; mi++)
#pragma unroll
        for (int ni = 0; ni < 8; ni++)
#pragma unroll
            for (int k = 0; k < 4; k++) acc[mi][ni][k] = 0.f;

    int kTiles = K >> 5;
    for (int kt = 0; kt < kTiles; ++kt) {
        int cur = kt & 1;
        char* bufp = smem + cur * BUF_BYTES;

#pragma unroll
        for (int i = 0; i < 4; i++) {
            uint32_t h0, l0, h1, l1;
            split2(avr[i].x, avr[i].y, h0, l0);
            split2(avr[i].z, avr[i].w, h1, l1);
            int off = arow * (SA_STRIDE * 2) + (acol + i * 4) * 2;
            *(uint2*)(bufp + off)           = make_uint2(h0, h1);
            *(uint2*)(bufp + A_BYTES + off) = make_uint2(l0, l1);
        }
#pragma unroll
        for (int i = 0; i < 4; i++) {
            uint32_t h0, l0, h1, l1;
            split2(bvr[i].x, bvr[i].y, h0, l0);
            split2(bvr[i].z, bvr[i].w, h1, l1);
            int off = brow * (SB_STRIDE * 2) + (bcol + i * 4) * 2;
            *(uint2*)(bufp + 2 * A_BYTES + off)           = make_uint2(h0, h1);
            *(uint2*)(bufp + 2 * A_BYTES + B_BYTES + off) = make_uint2(l0, l1);
        }
        __syncthreads();

        if (kt + 1 < kTiles) {
            Ag += 32;
            Bg += (size_t)32 * NW;
#pragma unroll
            for (int i = 0; i < 4; i++) avr[i] = *(const float4*)(Ag + i * 4);
#pragma unroll
            for (int i = 0; i < 4; i++) bvr[i] = *(const float4*)(Bg + i * 4);
        }

        uint32_t sA = sbase + cur * BUF_BYTES;
        uint32_t sB = sA + 2 * A_BYTES;
#pragma unroll
        for (int ks = 0; ks < 2; ks++) {
            uint32_t ah[2][4], al[2][4], bh[4][4], bl[4][4];
#pragma unroll
            for (int mi = 0; mi < 2; mi++) {
                uint32_t r = wm * 32 + mi * 16 + (lane & 15);
                uint32_t c = ks * 16 + ((lane >> 4) << 3);
                uint32_t addr = sA + (r * SA_STRIDE + c) * 2;
                ldsm4(ah[mi], addr);
                ldsm4(al[mi], addr + A_BYTES);
            }
#pragma unroll
            for (int nb = 0; nb < 4; nb++) {
                uint32_t r = ks * 16 + (lane & 15);
                uint32_t c = wn * 64 + nb * 16 + ((lane >> 4) << 3);
                uint32_t addr = sB + (r * SB_STRIDE + c) * 2;
                ldsm4t(bh[nb], addr);
                ldsm4t(bl[nb], addr + B_BYTES);
            }
#pragma unroll
            for (int mi = 0; mi < 2; mi++)
#pragma unroll
                for (int nb = 0; nb < 4; nb++)
#pragma unroll
                    for (int j = 0; j < 2; j++) {
                        int ni = nb * 2 + j;
                        mma16816(acc[mi][ni], ah[mi], bh[nb][2 * j], bh[nb][2 * j + 1]);
                        mma16816(acc[mi][ni], ah[mi], bl[nb][2 * j], bl[nb][2 * j + 1]);
                        mma16816(acc[mi][ni], al[mi], bh[nb][2 * j], bh[nb][2 * j + 1]);
                    }
        }
        __syncthreads();
    }

    // ---- fused epilogue: up warps -> smem, gate warps compute h -------------
    float* su = (float*)smem;          // 128 x 64 fp32 = 32 KB (buffers dead)
    int gq = lane >> 2, q = lane & 3;
    if (wn == 1) {
#pragma unroll
        for (int mi = 0; mi < 2; mi++) {
            int rl = wm * 32 + mi * 16 + gq;
#pragma unroll
            for (int ni = 0; ni < 8; ni++) {
                int c = ni * 8 + q * 2;
                su[rl * 64 + c]           = acc[mi][ni][0];
                su[rl * 64 + c + 1]       = acc[mi][ni][1];
                su[(rl + 8) * 64 + c]     = acc[mi][ni][2];
                su[(rl + 8) * 64 + c + 1] = acc[mi][ni][3];
            }
        }
    }
    __syncthreads();
    if (wn == 0) {
        float* H = g_h + (size_t)e * CAP * Fd;
#pragma unroll
        for (int mi = 0; mi < 2; mi++) {
            int rl = wm * 32 + mi * 16 + gq;
#pragma unroll
            for (int ni = 0; ni < 8; ni++) {
                int c = ni * 8 + q * 2;
                float u00 = su[rl * 64 + c];
                float u01 = su[rl * 64 + c + 1];
                float u10 = su[(rl + 8) * 64 + c];
                float u11 = su[(rl + 8) * 64 + c + 1];
                float g00 = acc[mi][ni][0], g01 = acc[mi][ni][1];
                float g10 = acc[mi][ni][2], g11 = acc[mi][ni][3];
                float2 v0, v1;
                v0.x = g00 / (1.f + expf(-g00)) * u00;
                v0.y = g01 / (1.f + expf(-g01)) * u01;
                v1.x = g10 / (1.f + expf(-g10)) * u10;
                v1.y = g11 / (1.f + expf(-g11)) * u11;
                size_t i0 = (size_t)(row0 + rl) * Fd + col0 + c;
                size_t i1 = i0 + (size_t)8 * Fd;
                *(float2*)&H[i0] = v0;
                *(float2*)&H[i1] = v1;
            }
        }
    }
}

// ---- down GEMM: y = h @ W2 (round-9 structure, mode-2 semantics) ------------
__global__ __launch_bounds__(256, 1) void mma_down(const float* __restrict__ W2) {
    const int K = Fd, N = Hd;
    int e = blockIdx.z;
    int row0 = blockIdx.y * 128;
    if (row0 >= g_active[e]) return;
    int col0 = blockIdx.x * 128;

    const float* A = g_h + (size_t)e * CAP * K;
    const float* B = W2 + (size_t)e * K * N;
    float*       C = g_y + (size_t)e * CAP * N;

    extern __shared__ char smem[];
    uint32_t sbase = (uint32_t)__cvta_generic_to_shared(smem);

    int tid  = threadIdx.x;
    int lane = tid & 31, wid = tid >> 5;
    int wm = wid >> 1, wn = wid & 1;

    int arow = tid >> 1, acol = (tid & 1) * 16;
    int brow = tid >> 3, bcol = (tid & 7) * 16;
    const float* Ag = A + (size_t)(row0 + arow) * K + acol;
    const float* Bg = B + (size_t)brow * N + col0 + bcol;

    float4 avr[4], bvr[4];
#pragma unroll
    for (int i = 0; i < 4; i++) avr[i] = *(const float4*)(Ag + i * 4);
#pragma unroll
    for (int i = 0; i < 4; i++) bvr[i] = *(const float4*)(Bg + i * 4);

    float acc[2][8][4];
#pragma unroll
    for (int mi = 0; mi < 2; mi++)
#pragma unroll
        for (int ni = 0; ni < 8; ni++)
#pragma unroll
            for (int k = 0; k < 4; k++) acc[mi][ni][k] = 0.f;

    int kTiles = K >> 5;
    for (int kt = 0; kt < kTiles; ++kt) {
        int cur = kt & 1;
        char* bufp = smem + cur * BUF_BYTES;

#pragma unroll
        for (int i = 0; i < 4; i++) {
            uint32_t h0, l0, h1, l1;
            split2(avr[i].x, avr[i].y, h0, l0);
            split2(avr[i].z, avr[i].w, h1, l1);
            int off = arow * (SA_STRIDE * 2) + (acol + i * 4) * 2;
            *(uint2*)(bufp + off)           = make_uint2(h0, h1);
            *(uint2*)(bufp + A_BYTES + off) = make_uint2(l0, l1);
        }
#pragma unroll
        for (int i = 0; i < 4; i++) {
            uint32_t h0, l0, h1, l1;
            split2(bvr[i].x, bvr[i].y, h0, l0);
            split2(bvr[i].z, bvr[i].w, h1, l1);
            int off = brow * (SB_STRIDE * 2) + (bcol + i * 4) * 2;
            *(uint2*)(bufp + 2 * A_BYTES + off)           = make_uint2(h0, h1);
            *(uint2*)(bufp + 2 * A_BYTES + B_BYTES + off) = make_uint2(l0, l1);
        }
        __syncthreads();

        if (kt + 1 < kTiles) {
            Ag += 32;
            Bg += (size_t)32 * N;
#pragma unroll
            for (int i = 0; i < 4; i++) avr[i] = *(const float4*)(Ag + i * 4);
#pragma unroll
            for (int i = 0; i < 4; i++) bvr[i] = *(const float4*)(Bg + i * 4);
        }

        uint32_t sA = sbase + cur * BUF_BYTES;
        uint32_t sB = sA + 2 * A_BYTES;
#pragma unroll
        for (int ks = 0; ks < 2; ks++) {
            uint32_t ah[2][4], al[2][4], bh[4][4], bl[4][4];
#pragma unroll
            for (int mi = 0; mi < 2; mi++) {
                uint32_t r = wm * 32 + mi * 16 + (lane & 15);
                uint32_t c = ks * 16 + ((lane >> 4) << 3);
                uint32_t addr = sA + (r * SA_STRIDE + c) * 2;
                ldsm4(ah[mi], addr);
                ldsm4(al[mi], addr + A_BYTES);
            }
#pragma unroll
            for (int nb = 0; nb < 4; nb++) {
                uint32_t r = ks * 16 + (lane & 15);
                uint32_t c = wn * 64 + nb * 16 + ((lane >> 4) << 3);
                uint32_t addr = sB + (r * SB_STRIDE + c) * 2;
                ldsm4t(bh[nb], addr);
                ldsm4t(bl[nb], addr + B_BYTES);
            }
#pragma unroll
            for (int mi = 0; mi < 2; mi++)
#pragma unroll
                for (int nb = 0; nb < 4; nb++)
#pragma unroll
                    for (int j = 0; j < 2; j++) {
                        int ni = nb * 2 + j;
                        mma16816(acc[mi][ni], ah[mi], bh[nb][2 * j], bh[nb][2 * j + 1]);
                        mma16816(acc[mi][ni], ah[mi], bl[nb][2 * j], bl[nb][2 * j + 1]);
                        mma16816(acc[mi][ni], al[mi], bh[nb][2 * j], bh[nb][2 * j + 1]);
                    }
        }
        __syncthreads();
    }

    int gq = lane >> 2, q = lane & 3;
#pragma unroll
    for (int mi = 0; mi < 2; mi++) {
        int r = row0 + wm * 32 + mi * 16 + gq;
#pragma unroll
        for (int ni = 0; ni < 8; ni++) {
            int c = col0 + wn * 64 + ni * 8 + q * 2;
            size_t i0 = (size_t)r * N + c;
            size_t i1 = i0 + (size_t)8 * N;
            *(float2*)&C[i0] = make_float2(acc[mi][ni][0], acc[mi][ni][1]);
            *(float2*)&C[i1] = make_float2(acc[mi][ni][2], acc[mi][ni][3]);
        }
    }
}

// ---------------- combine ----------------------------------------------------
__global__ void combine_kernel(float* __restrict__ out) {
    int t = blockIdx.x;
    int tid = threadIdx.x;
    int n0 = 2 * t, n1 = 2 * t + 1;
    float w0 = g_w[n0], w1 = g_w[n1];
    const float4* y0 = (const float4*)(g_y + ((size_t)g_fe[n0] * CAP + g_pos[n0]) * Hd);
    const float4* y1 = (const float4*)(g_y + ((size_t)g_fe[n1] * CAP + g_pos[n1]) * Hd);
    float4 a = y0[tid], b = y1[tid];
    float4 o;
    o.x = w0 * a.x + w1 * b.x;
    o.y = w0 * a.y + w1 * b.y;
    o.z = w0 * a.z + w1 * b.z;
    o.w = w0 * a.w + w1 * b.w;
    ((float4*)(out + (size_t)t * Hd))[tid] = o;
}

// ---------------- aux loss -----------------------------------------------------
__global__ void aux_kernel(float* __restrict__ out, int out_size) {
    if (threadIdx.x == 0) {
        float s = 0.f;
#pragma unroll
        for (int e = 0; e < NE; e++) s += g_imp[e] * (float)g_load[e];
        float aux = (float)NE * s / (float)(Tt * 2);
        if (out_size > Tt * Hd) out[(size_t)Tt * Hd] = aux;
    }
}

// ---------------- launch -------------------------------------------------------
extern "C" void kernel_launch(void* const* d_in, const int* in_sizes, int n_in,
                              void* d_out, int out_size) {
    const float* x  = (const float*)d_in[0];
    const float* Wr = (const float*)d_in[1];
    const float* Wg = (const float*)d_in[2];
    const float* Wu = (const float*)d_in[3];
    const float* W2 = (const float*)d_in[4];
    float* out = (float*)d_out;

    int smem_bytes = SMEM_GEMM;
    cudaFuncSetAttribute(mma_fused, cudaFuncAttributeMaxDynamicSharedMemorySize, smem_bytes);
    cudaFuncSetAttribute(mma_down,  cudaFuncAttributeMaxDynamicSharedMemorySize, smem_bytes);

    zero_kernel<<<1, 32>>>();
    router_kernel<<<Tt / 8, 256>>>(x, Wr);
    build_lists<<<NSLOT / 256, 256>>>();
    finalize_kernel<<<1, 32>>>();
    rank_kernel<<<dim3(NSLOT / 256, NE), 256>>>();
    scatter_kernel<<<NSLOT, 128>>>(x);

    dim3 grid_fused(Fd / 64, CAP / 128, NE);   // 32 x 40 x 8
    dim3 grid_down (Hd / 128, CAP / 128, NE);  //  8 x 40 x 8

    mma_fused<<<grid_fused, 256, smem_bytes>>>(Wg, Wu);  // h = silu(x@Wg)*(x@Wu)
    mma_down <<<grid_down, 256, smem_bytes>>>(W2);       // y = h @ W2

    combine_kernel<<<Tt, 256>>>(out);
    aux_kernel<<<1, 32>>>(out, out_size);
}

// round 14
// speedup vs baseline: 1.2348x; 1.0255x over previous
#include <cuda_runtime.h>
#include <cuda_bf16.h>
#include <math.h>
#include <stdint.h>

// Problem constants (B=2, S=8192 -> T=16384), H=1024, F=2048, E=8, K=2
#define Tt    16384
#define Hd    1024
#define Fd    2048
#define NE    8
#define NSLOT 32768          // T * K
#define CAP   5120           // ceil(1.25 * T * K / E) -- exactly 40 * 128

// ---------------- static device scratch (no runtime allocation) -------------
#define XN4 (NE * CAP * Hd / 8)   // uint4 count (8 bf16 each)
#define HN4 (NE * CAP * Fd / 8)
__device__ uint4 g_xhi4[XN4];              // dispatched x, bf16 hi plane
__device__ uint4 g_xlo4[XN4];              // dispatched x, bf16 lo plane
__device__ uint4 g_hhi4[HN4];              // h = silu(g)*u, bf16 hi plane
__device__ uint4 g_hlo4[HN4];              // h lo plane
__device__ float g_y[NE * CAP * Hd];
__device__ unsigned long long g_keys[NE * NSLOT];
__device__ int   g_cnt[NE];
__device__ int   g_active[NE];
__device__ float g_imp[NE];
__device__ int   g_load[NE];
__device__ int   g_fe[NSLOT];
__device__ float g_fp[NSLOT];
__device__ int   g_pos[NSLOT];
__device__ float g_w[NSLOT];

// ---------------- truncation split: exact, packs 2 elems -------------------
__device__ __forceinline__ void split2(float x, float y, uint32_t& hi, uint32_t& lo) {
    uint32_t ux = __float_as_uint(x);
    uint32_t uy = __float_as_uint(y);
    hi = __byte_perm(ux, uy, 0x7632);                   // {trunc16(x), trunc16(y)}
    float lx = x - __uint_as_float(ux & 0xFFFF0000u);   // exact residual
    float ly = y - __uint_as_float(uy & 0xFFFF0000u);
    asm("cvt.rn.bf16x2.f32 %0, %1, %2;" : "=r"(lo) : "f"(ly), "f"(lx));
}

// ---------------- per-launch counter reset ---------------------------------
__global__ void zero_kernel() {
    int i = threadIdx.x;
    if (i < NE) { g_cnt[i] = 0; g_imp[i] = 0.f; g_load[i] = 0; }
}

// ---------------- router ----------------------------------------------------
__global__ void router_kernel(const float* __restrict__ x,
                              const float* __restrict__ Wr) {
    __shared__ float sWr[Hd * NE];
    __shared__ float s_imp[NE];
    __shared__ int   s_load[NE];
    int tid = threadIdx.x;
    if (tid < NE) { s_imp[tid] = 0.f; s_load[tid] = 0; }
    for (int i = tid; i < Hd * NE / 4; i += 256)
        ((float4*)sWr)[i] = ((const float4*)Wr)[i];
    __syncthreads();

    int warp = tid >> 5, lane = tid & 31;
    int t = blockIdx.x * 8 + warp;

    float acc[NE];
#pragma unroll
    for (int e = 0; e < NE; e++) acc[e] = 0.f;

    const float* xr = x + (size_t)t * Hd;
    for (int j = lane; j < Hd; j += 32) {
        float xv = xr[j];
#pragma unroll
        for (int e = 0; e < NE; e++) acc[e] += xv * sWr[j * NE + e];
    }
#pragma unroll
    for (int o = 16; o; o >>= 1)
#pragma unroll
        for (int e = 0; e < NE; e++)
            acc[e] += __shfl_xor_sync(0xffffffffu, acc[e], o);

    if (lane == 0) {
        float mx = acc[0];
#pragma unroll
        for (int e = 1; e < NE; e++) mx = fmaxf(mx, acc[e]);
        float pe[NE], s = 0.f;
#pragma unroll
        for (int e = 0; e < NE; e++) { pe[e] = expf(acc[e] - mx); s += pe[e]; }
        float inv = 1.f / s;
#pragma unroll
        for (int e = 0; e < NE; e++) { pe[e] *= inv; atomicAdd(&s_imp[e], pe[e]); }
        int e0 = 0;
#pragma unroll
        for (int e = 1; e < NE; e++) if (pe[e] > pe[e0]) e0 = e;
        int e1 = (e0 == 0) ? 1 : 0;
#pragma unroll
        for (int e = 0; e < NE; e++)
            if (e != e0 && e != e1 && pe[e] > pe[e1]) e1 = e;
        atomicAdd(&s_load[e0], 1);
        atomicAdd(&s_load[e1], 1);
        float ps = pe[e0] + pe[e1];
        g_fe[2 * t]     = e0;
        g_fe[2 * t + 1] = e1;
        g_fp[2 * t]     = pe[e0] / ps;
        g_fp[2 * t + 1] = pe[e1] / ps;
    }
    __syncthreads();
    if (tid < NE) {
        atomicAdd(&g_imp[tid], s_imp[tid]);
        atomicAdd(&g_load[tid], s_load[tid]);
    }
}

// ---------------- group slots by expert: packed keys -------------------------
__global__ void build_lists() {
    int n = blockIdx.x * 256 + threadIdx.x;
    if (n >= NSLOT) return;
    int e = g_fe[n];
    int i = atomicAdd(&g_cnt[e], 1);
    unsigned long long key =
        ((unsigned long long)__float_as_uint(g_fp[n]) << 32) |
        (unsigned int)(NSLOT - 1 - n);
    g_keys[e * NSLOT + i] = key;
}

__global__ void finalize_kernel() {
    int e = threadIdx.x;
    if (e < NE) g_active[e] = min(g_cnt[e], CAP);
}

// ---------------- rank: smem-tiled exact descending rank ---------------------
__global__ void rank_kernel() {
    int e = blockIdx.y;
    int c = g_cnt[e];
    int base = blockIdx.x * 256;
    if (base >= c) return;
    __shared__ unsigned long long sk[512];
    int tid = threadIdx.x;
    int idx = base + tid;
    bool act = idx < c;
    unsigned long long key = 0;
    if (act) key = g_keys[e * NSLOT + idx];
    int r = 0;
    for (int chunk = 0; chunk < c; chunk += 512) {
        int m = min(512, c - chunk);
        for (int i = tid; i < m; i += 256)
            sk[i] = g_keys[e * NSLOT + chunk + i];
        __syncthreads();
        if (act)
            for (int i = 0; i < m; i++)
                if (sk[i] > key) r++;
        __syncthreads();
    }
    if (act) {
        int n = NSLOT - 1 - (int)(unsigned int)(key & 0xFFFFFFFFu);
        float p = __uint_as_float((unsigned int)(key >> 32));
        bool keep = r < CAP;
        g_pos[n] = keep ? r : (CAP - 1);
        g_w[n]   = keep ? p : 0.f;
    }
}

// ---------------- dispatch: gather + split x into bf16 hi/lo planes ----------
__global__ void scatter_kernel(const float* __restrict__ x) {
    int n = blockIdx.x;
    float w = g_w[n];
    if (w == 0.f) return;
    int e = g_fe[n], pos = g_pos[n];
    int t = n >> 1;
    const float4* src = (const float4*)(x + (size_t)t * Hd);
    int tid = threadIdx.x;             // 128 threads, 8 floats each
    float4 a = src[2 * tid], b = src[2 * tid + 1];
    uint32_t h0, l0, h1, l1, h2, l2, h3, l3;
    split2(a.x, a.y, h0, l0);
    split2(a.z, a.w, h1, l1);
    split2(b.x, b.y, h2, l2);
    split2(b.z, b.w, h3, l3);
    size_t ub = ((size_t)e * CAP + pos) * (Hd / 8) + tid;
    g_xhi4[ub] = make_uint4(h0, h1, h2, h3);
    g_xlo4[ub] = make_uint4(l0, l1, l2, l3);
}

// ================= bf16x3 tensor-core grouped GEMM ===========================
// Round-9 proven shape: block 128x128x32, 8 warps (4x2), warp tile 32x64,
// two barriers per k-tile, acc += hh + hl + lh.
// A operands (x, h) are PRE-SPLIT bf16 hi/lo planes: staging is pure uint4
// copy. B operands (weights) split in-loop as before.

#define SA_STRIDE 40
#define SB_STRIDE 136
#define A_BYTES   10240   // 128 * 80
#define B_BYTES   8704    // 32 * 272
#define BUF_BYTES 37888
#define SMEM_GEMM 75776

__device__ __forceinline__ void ldsm4(uint32_t* r, uint32_t addr) {
    asm volatile("ldmatrix.sync.aligned.m8n8.x4.shared.b16 {%0,%1,%2,%3}, [%4];"
        : "=r"(r[0]), "=r"(r[1]), "=r"(r[2]), "=r"(r[3]) : "r"(addr));
}
__device__ __forceinline__ void ldsm4t(uint32_t* r, uint32_t addr) {
    asm volatile("ldmatrix.sync.aligned.m8n8.x4.trans.shared.b16 {%0,%1,%2,%3}, [%4];"
        : "=r"(r[0]), "=r"(r[1]), "=r"(r[2]), "=r"(r[3]) : "r"(addr));
}
__device__ __forceinline__ void mma16816(float* d, const uint32_t* a, uint32_t b0, uint32_t b1) {
    asm volatile("mma.sync.aligned.m16n8k16.row.col.f32.bf16.bf16.f32 "
        "{%0,%1,%2,%3}, {%4,%5,%6,%7}, {%8,%9}, {%0,%1,%2,%3};"
        : "+f"(d[0]), "+f"(d[1]), "+f"(d[2]), "+f"(d[3])
        : "r"(a[0]), "r"(a[1]), "r"(a[2]), "r"(a[3]), "r"(b0), "r"(b1));
}

// ---- FUSED gate+up GEMM ------------------------------------------------------
// col0 = blockIdx.x * 64 covers 64 cols of BOTH Wg and Wu. Smem B cols [0,64)
// <- Wg, [64,128) <- Wu. Warps wn=0 gate, wn=1 up. Epilogue computes
// h = silu(g)*u once and writes bf16 hi/lo planes.
__global__ __launch_bounds__(256, 1) void mma_fused(
    const float* __restrict__ Wg, const float* __restrict__ Wu) {
    const int K = Hd, NW = Fd;
    int e = blockIdx.z;
    int row0 = blockIdx.y * 128;
    if (row0 >= g_active[e]) return;
    int col0 = blockIdx.x * 64;

    const __nv_bfloat16* Ahp = (const __nv_bfloat16*)g_xhi4 + (size_t)e * CAP * K;
    const __nv_bfloat16* Alp = (const __nv_bfloat16*)g_xlo4 + (size_t)e * CAP * K;

    extern __shared__ char smem[];
    uint32_t sbase = (uint32_t)__cvta_generic_to_shared(smem);

    int tid  = threadIdx.x;
    int lane = tid & 31, wid = tid >> 5;
    int wm = wid >> 1, wn = wid & 1;

    int arow = tid >> 1, acol = (tid & 1) * 16;
    int brow = tid >> 3, bsub = tid & 7;
    int bcol = bsub * 16;
    const float* Bmat = (bsub < 4) ? Wg : Wu;
    int gcol = col0 + (bcol & 63);
    const __nv_bfloat16* Agh = Ahp + (size_t)(row0 + arow) * K + acol;
    const __nv_bfloat16* Agl = Alp + (size_t)(row0 + arow) * K + acol;
    const float* Bg = Bmat + (size_t)e * K * NW + (size_t)brow * NW + gcol;

    uint4 arh[2], arl[2];
    float4 bvr[4];
    arh[0] = *(const uint4*)Agh;  arh[1] = *(const uint4*)(Agh + 8);
    arl[0] = *(const uint4*)Agl;  arl[1] = *(const uint4*)(Agl + 8);
#pragma unroll
    for (int i = 0; i < 4; i++) bvr[i] = *(const float4*)(Bg + i * 4);

    float acc[2][8][4];
#pragma unroll
    for (int mi = 0; mi < 2; mi++)
#pragma unroll
        for (int ni = 0; ni < 8; ni++)
#pragma unroll
            for (int k = 0; k < 4; k++) acc[mi][ni][k] = 0.f;

    int offA = arow * 80 + acol * 2;
    int kTiles = K >> 5;
    for (int kt = 0; kt < kTiles; ++kt) {
        int cur = kt & 1;
        char* bufp = smem + cur * BUF_BYTES;

        // A: pure copy of pre-split planes
        *(uint4*)(bufp + offA)                = arh[0];
        *(uint4*)(bufp + offA + 16)           = arh[1];
        *(uint4*)(bufp + A_BYTES + offA)      = arl[0];
        *(uint4*)(bufp + A_BYTES + offA + 16) = arl[1];
        // B: in-loop truncation split
#pragma unroll
        for (int i = 0; i < 4; i++) {
            uint32_t h0, l0, h1, l1;
            split2(bvr[i].x, bvr[i].y, h0, l0);
            split2(bvr[i].z, bvr[i].w, h1, l1);
            int off = brow * (SB_STRIDE * 2) + (bcol + i * 4) * 2;
            *(uint2*)(bufp + 2 * A_BYTES + off)           = make_uint2(h0, h1);
            *(uint2*)(bufp + 2 * A_BYTES + B_BYTES + off) = make_uint2(l0, l1);
        }
        __syncthreads();

        if (kt + 1 < kTiles) {
            Agh += 32; Agl += 32;
            Bg += (size_t)32 * NW;
            arh[0] = *(const uint4*)Agh;  arh[1] = *(const uint4*)(Agh + 8);
            arl[0] = *(const uint4*)Agl;  arl[1] = *(const uint4*)(Agl + 8);
#pragma unroll
            for (int i = 0; i < 4; i++) bvr[i] = *(const float4*)(Bg + i * 4);
        }

        uint32_t sA = sbase + cur * BUF_BYTES;
        uint32_t sB = sA + 2 * A_BYTES;
#pragma unroll
        for (int ks = 0; ks < 2; ks++) {
            uint32_t ah[2][4], al[2][4], bh[4][4], bl[4][4];
#pragma unroll
            for (int mi = 0; mi < 2; mi++) {
                uint32_t r = wm * 32 + mi * 16 + (lane & 15);
                uint32_t c = ks * 16 + ((lane >> 4) << 3);
                uint32_t addr = sA + (r * SA_STRIDE + c) * 2;
                ldsm4(ah[mi], addr);
                ldsm4(al[mi], addr + A_BYTES);
            }
#pragma unroll
            for (int nb = 0; nb < 4; nb++) {
                uint32_t r = ks * 16 + (lane & 15);
                uint32_t c = wn * 64 + nb * 16 + ((lane >> 4) << 3);
                uint32_t addr = sB + (r * SB_STRIDE + c) * 2;
                ldsm4t(bh[nb], addr);
                ldsm4t(bl[nb], addr + B_BYTES);
            }
#pragma unroll
            for (int mi = 0; mi < 2; mi++)
#pragma unroll
                for (int nb = 0; nb < 4; nb++)
#pragma unroll
                    for (int j = 0; j < 2; j++) {
                        int ni = nb * 2 + j;
                        mma16816(acc[mi][ni], ah[mi], bh[nb][2 * j], bh[nb][2 * j + 1]);
                        mma16816(acc[mi][ni], ah[mi], bl[nb][2 * j], bl[nb][2 * j + 1]);
                        mma16816(acc[mi][ni], al[mi], bh[nb][2 * j], bh[nb][2 * j + 1]);
                    }
        }
        __syncthreads();
    }

    // ---- fused epilogue: up warps -> smem, gate warps compute h -> planes ----
    float* su = (float*)smem;          // 128 x 64 fp32 = 32 KB
    int gq = lane >> 2, q = lane & 3;
    if (wn == 1) {
#pragma unroll
        for (int mi = 0; mi < 2; mi++) {
            int rl = wm * 32 + mi * 16 + gq;
#pragma unroll
            for (int ni = 0; ni < 8; ni++) {
                int c = ni * 8 + q * 2;
                su[rl * 64 + c]           = acc[mi][ni][0];
                su[rl * 64 + c + 1]       = acc[mi][ni][1];
                su[(rl + 8) * 64 + c]     = acc[mi][ni][2];
                su[(rl + 8) * 64 + c + 1] = acc[mi][ni][3];
            }
        }
    }
    __syncthreads();
    if (wn == 0) {
        __nv_bfloat16* HH = (__nv_bfloat16*)g_hhi4 + (size_t)e * CAP * Fd;
        __nv_bfloat16* HL = (__nv_bfloat16*)g_hlo4 + (size_t)e * CAP * Fd;
#pragma unroll
        for (int mi = 0; mi < 2; mi++) {
            int rl = wm * 32 + mi * 16 + gq;
#pragma unroll
            for (int ni = 0; ni < 8; ni++) {
                int c = ni * 8 + q * 2;
                float u00 = su[rl * 64 + c];
                float u01 = su[rl * 64 + c + 1];
                float u10 = su[(rl + 8) * 64 + c];
                float u11 = su[(rl + 8) * 64 + c + 1];
                float g00 = acc[mi][ni][0], g01 = acc[mi][ni][1];
                float g10 = acc[mi][ni][2], g11 = acc[mi][ni][3];
                float h00 = g00 / (1.f + expf(-g00)) * u00;
                float h01 = g01 / (1.f + expf(-g01)) * u01;
                float h10 = g10 / (1.f + expf(-g10)) * u10;
                float h11 = g11 / (1.f + expf(-g11)) * u11;
                uint32_t hp0, lp0, hp1, lp1;
                split2(h00, h01, hp0, lp0);
                split2(h10, h11, hp1, lp1);
                size_t i0 = (size_t)(row0 + rl) * Fd + col0 + c;
                size_t i1 = i0 + (size_t)8 * Fd;
                *(uint32_t*)&HH[i0] = hp0;
                *(uint32_t*)&HL[i0] = lp0;
                *(uint32_t*)&HH[i1] = hp1;
                *(uint32_t*)&HL[i1] = lp1;
            }
        }
    }
}

// ---- down GEMM: y = h @ W2, A from pre-split h planes ------------------------
__global__ __launch_bounds__(256, 1) void mma_down(const float* __restrict__ W2) {
    const int K = Fd, N = Hd;
    int e = blockIdx.z;
    int row0 = blockIdx.y * 128;
    if (row0 >= g_active[e]) return;
    int col0 = blockIdx.x * 128;

    const __nv_bfloat16* Ahp = (const __nv_bfloat16*)g_hhi4 + (size_t)e * CAP * K;
    const __nv_bfloat16* Alp = (const __nv_bfloat16*)g_hlo4 + (size_t)e * CAP * K;
    const float* B = W2 + (size_t)e * K * N;
    float*       C = g_y + (size_t)e * CAP * N;

    extern __shared__ char smem[];
    uint32_t sbase = (uint32_t)__cvta_generic_to_shared(smem);

    int tid  = threadIdx.x;
    int lane = tid & 31, wid = tid >> 5;
    int wm = wid >> 1, wn = wid & 1;

    int arow = tid >> 1, acol = (tid & 1) * 16;
    int brow = tid >> 3, bcol = (tid & 7) * 16;
    const __nv_bfloat16* Agh = Ahp + (size_t)(row0 + arow) * K + acol;
    const __nv_bfloat16* Agl = Alp + (size_t)(row0 + arow) * K + acol;
    const float* Bg = B + (size_t)brow * N + col0 + bcol;

    uint4 arh[2], arl[2];
    float4 bvr[4];
    arh[0] = *(const uint4*)Agh;  arh[1] = *(const uint4*)(Agh + 8);
    arl[0] = *(const uint4*)Agl;  arl[1] = *(const uint4*)(Agl + 8);
#pragma unroll
    for (int i = 0; i < 4; i++) bvr[i] = *(const float4*)(Bg + i * 4);

    float acc[2][8][4];
#pragma unroll
    for (int mi = 0; mi < 2; mi++)
#pragma unroll
        for (int ni = 0; ni < 8; ni++)
#pragma unroll
            for (int k = 0; k < 4; k++) acc[mi][ni][k] = 0.f;

    int offA = arow * 80 + acol * 2;
    int kTiles = K >> 5;
    for (int kt = 0; kt < kTiles; ++kt) {
        int cur = kt & 1;
        char* bufp = smem + cur * BUF_BYTES;

        *(uint4*)(bufp + offA)                = arh[0];
        *(uint4*)(bufp + offA + 16)           = arh[1];
        *(uint4*)(bufp + A_BYTES + offA)      = arl[0];
        *(uint4*)(bufp + A_BYTES + offA + 16) = arl[1];
#pragma unroll
        for (int i = 0; i < 4; i++) {
            uint32_t h0, l0, h1, l1;
            split2(bvr[i].x, bvr[i].y, h0, l0);
            split2(bvr[i].z, bvr[i].w, h1, l1);
            int off = brow * (SB_STRIDE * 2) + (bcol + i * 4) * 2;
            *(uint2*)(bufp + 2 * A_BYTES + off)           = make_uint2(h0, h1);
            *(uint2*)(bufp + 2 * A_BYTES + B_BYTES + off) = make_uint2(l0, l1);
        }
        __syncthreads();

        if (kt + 1 < kTiles) {
            Agh += 32; Agl += 32;
            Bg += (size_t)32 * N;
            arh[0] = *(const uint4*)Agh;  arh[1] = *(const uint4*)(Agh + 8);
            arl[0] = *(const uint4*)Agl;  arl[1] = *(const uint4*)(Agl + 8);
#pragma unroll
            for (int i = 0; i < 4; i++) bvr[i] = *(const float4*)(Bg + i * 4);
        }

        uint32_t sA = sbase + cur * BUF_BYTES;
        uint32_t sB = sA + 2 * A_BYTES;
#pragma unroll
        for (int ks = 0; ks < 2; ks++) {
            uint32_t ah[2][4], al[2][4], bh[4][4], bl[4][4];
#pragma unroll
            for (int mi = 0; mi < 2; mi++) {
                uint32_t r = wm * 32 + mi * 16 + (lane & 15);
                uint32_t c = ks * 16 + ((lane >> 4) << 3);
                uint32_t addr = sA + (r * SA_STRIDE + c) * 2;
                ldsm4(ah[mi], addr);
                ldsm4(al[mi], addr + A_BYTES);
            }
#pragma unroll
            for (int nb = 0; nb < 4; nb++) {
                uint32_t r = ks * 16 + (lane & 15);
                uint32_t c = wn * 64 + nb * 16 + ((lane >> 4) << 3);
                uint32_t addr = sB + (r * SB_STRIDE + c) * 2;
                ldsm4t(bh[nb], addr);
                ldsm4t(bl[nb], addr + B_BYTES);
            }
#pragma unroll
            for (int mi = 0; mi < 2; mi++)
#pragma unroll
                for (int nb = 0; nb < 4; nb++)
#pragma unroll
                    for (int j = 0; j < 2; j++) {
                        int ni = nb * 2 + j;
                        mma16816(acc[mi][ni], ah[mi], bh[nb][2 * j], bh[nb][2 * j + 1]);
                        mma16816(acc[mi][ni], ah[mi], bl[nb][2 * j], bl[nb][2 * j + 1]);
                        mma16816(acc[mi][ni], al[mi], bh[nb][2 * j], bh[nb][2 * j + 1]);
                    }
        }
        __syncthreads();
    }

    int gq = lane >> 2, q = lane & 3;
#pragma unroll
    for (int mi = 0; mi < 2; mi++) {
        int r = row0 + wm * 32 + mi * 16 + gq;
#pragma unroll
        for (int ni = 0; ni < 8; ni++) {
            int c = col0 + wn * 64 + ni * 8 + q * 2;
            size_t i0 = (size_t)r * N + c;
            size_t i1 = i0 + (size_t)8 * N;
            *(float2*)&C[i0] = make_float2(acc[mi][ni][0], acc[mi][ni][1]);
            *(float2*)&C[i1] = make_float2(acc[mi][ni][2], acc[mi][ni][3]);
        }
    }
}

// ---------------- combine ----------------------------------------------------
__global__ void combine_kernel(float* __restrict__ out) {
    int t = blockIdx.x;
    int tid = threadIdx.x;
    int n0 = 2 * t, n1 = 2 * t + 1;
    float w0 = g_w[n0], w1 = g_w[n1];
    const float4* y0 = (const float4*)(g_y + ((size_t)g_fe[n0] * CAP + g_pos[n0]) * Hd);
    const float4* y1 = (const float4*)(g_y + ((size_t)g_fe[n1] * CAP + g_pos[n1]) * Hd);
    float4 a = y0[tid], b = y1[tid];
    float4 o;
    o.x = w0 * a.x + w1 * b.x;
    o.y = w0 * a.y + w1 * b.y;
    o.z = w0 * a.z + w1 * b.z;
    o.w = w0 * a.w + w1 * b.w;
    ((float4*)(out + (size_t)t * Hd))[tid] = o;
}

// ---------------- aux loss -----------------------------------------------------
__global__ void aux_kernel(float* __restrict__ out, int out_size) {
    if (threadIdx.x == 0) {
        float s = 0.f;
#pragma unroll
        for (int e = 0; e < NE; e++) s += g_imp[e] * (float)g_load[e];
        float aux = (float)NE * s / (float)(Tt * 2);
        if (out_size > Tt * Hd) out[(size_t)Tt * Hd] = aux;
    }
}

// ---------------- launch -------------------------------------------------------
extern "C" void kernel_launch(void* const* d_in, const int* in_sizes, int n_in,
                              void* d_out, int out_size) {
    const float* x  = (const float*)d_in[0];
    const float* Wr = (const float*)d_in[1];
    const float* Wg = (const float*)d_in[2];
    const float* Wu = (const float*)d_in[3];
    const float* W2 = (const float*)d_in[4];
    float* out = (float*)d_out;

    int smem_bytes = SMEM_GEMM;
    cudaFuncSetAttribute(mma_fused, cudaFuncAttributeMaxDynamicSharedMemorySize, smem_bytes);
    cudaFuncSetAttribute(mma_down,  cudaFuncAttributeMaxDynamicSharedMemorySize, smem_bytes);

    zero_kernel<<<1, 32>>>();
    router_kernel<<<Tt / 8, 256>>>(x, Wr);
    build_lists<<<NSLOT / 256, 256>>>();
    finalize_kernel<<<1, 32>>>();
    rank_kernel<<<dim3(NSLOT / 256, NE), 256>>>();
    scatter_kernel<<<NSLOT, 128>>>(x);

    dim3 grid_fused(Fd / 64, CAP / 128, NE);   // 32 x 40 x 8
    dim3 grid_down (Hd / 128, CAP / 128, NE);  //  8 x 40 x 8

    mma_fused<<<grid_fused, 256, smem_bytes>>>(Wg, Wu);  // h = silu(x@Wg)*(x@Wu)
    mma_down <<<grid_down, 256, smem_bytes>>>(W2);       // y = h @ W2

    combine_kernel<<<Tt, 256>>>(out);
    aux_kernel<<<1, 32>>>(out, out_size);
}